// round 1
// baseline (speedup 1.0000x reference)
#include <cuda_runtime.h>
#include <math.h>

// Problem dims
#define BB 64
#define SS 512
#define II 512
#define HH 1024
#define OO 512
#define NBLK 128   // persistent grid size (<=148 SMs, 1 CTA/SM => co-resident)

// Scratch (static __device__ allocations are allowed; cudaMalloc is not)
__device__ float g_xi[SS * BB * HH];   // [s][b][h] : x@Wi^T + bi + bh
__device__ float g_hs[SS * BB * HH];   // [s][b][h] : hidden states
__device__ unsigned g_bar;             // grid barrier counter (monotonic)

__global__ void reset_bar_kernel() { g_bar = 0u; }

// ---------------------------------------------------------------------------
// Tiled fp32 GEMM, C = A(MxK) * Bw(NxK)^T + bias, NT layout (both K-contig).
// MODE 0: A = x, write g_xi[s][b][n] with m = b*SS+s, bias = bi[n]+bh[n]
// MODE 1: A = g_hs, write C[b*SS*OO + s*OO + n] with m = s*BB+b, bias = b1[n]
// Tile: 128(M) x 64(N) x 16(K), 256 threads, 8x4 per-thread micro-tile.
// ---------------------------------------------------------------------------
template <int MODE>
__global__ __launch_bounds__(256)
void gemm_nt_kernel(const float* __restrict__ A, const float* __restrict__ Bw,
                    const float* __restrict__ b1, const float* __restrict__ b2,
                    float* __restrict__ C, int K)
{
    __shared__ float As[16 * 132];  // transposed [k][m], pad 132
    __shared__ float Bs[16 * 68];   // transposed [k][n], pad 68

    const int tid = threadIdx.x;
    const int m0 = blockIdx.x * 128;
    const int n0 = blockIdx.y * 64;
    const int tx = tid & 15;        // n-direction (4 cols each)
    const int ty = tid >> 4;        // m-direction (8 rows each)
    const int r  = tid >> 2;        // 0..63 load row
    const int c4 = (tid & 3) * 4;   // 0,4,8,12 load k-col

    const float* Abase = (MODE == 0) ? A : (const float*)g_hs;

    float acc[8][4];
#pragma unroll
    for (int i = 0; i < 8; i++)
#pragma unroll
        for (int j = 0; j < 4; j++) acc[i][j] = 0.f;

    const float* Ap0 = Abase + (size_t)(m0 + r) * K + c4;
    const float* Ap1 = Abase + (size_t)(m0 + r + 64) * K + c4;
    const float* Bp  = Bw    + (size_t)(n0 + r) * K + c4;

    for (int k0 = 0; k0 < K; k0 += 16) {
        float4 av0 = *(const float4*)(Ap0 + k0);
        float4 av1 = *(const float4*)(Ap1 + k0);
        float4 bv  = *(const float4*)(Bp  + k0);
        __syncthreads();
        As[(c4 + 0) * 132 + r] = av0.x;
        As[(c4 + 1) * 132 + r] = av0.y;
        As[(c4 + 2) * 132 + r] = av0.z;
        As[(c4 + 3) * 132 + r] = av0.w;
        As[(c4 + 0) * 132 + r + 64] = av1.x;
        As[(c4 + 1) * 132 + r + 64] = av1.y;
        As[(c4 + 2) * 132 + r + 64] = av1.z;
        As[(c4 + 3) * 132 + r + 64] = av1.w;
        Bs[(c4 + 0) * 68 + r] = bv.x;
        Bs[(c4 + 1) * 68 + r] = bv.y;
        Bs[(c4 + 2) * 68 + r] = bv.z;
        Bs[(c4 + 3) * 68 + r] = bv.w;
        __syncthreads();
#pragma unroll
        for (int kk = 0; kk < 16; kk++) {
            float4 a0 = *(const float4*)&As[kk * 132 + ty * 8];
            float4 a1 = *(const float4*)&As[kk * 132 + ty * 8 + 4];
            float4 b  = *(const float4*)&Bs[kk * 68 + tx * 4];
            float am[8] = {a0.x, a0.y, a0.z, a0.w, a1.x, a1.y, a1.z, a1.w};
            float bn[4] = {b.x, b.y, b.z, b.w};
#pragma unroll
            for (int i = 0; i < 8; i++)
#pragma unroll
                for (int j = 0; j < 4; j++) acc[i][j] += am[i] * bn[j];
        }
    }

#pragma unroll
    for (int j = 0; j < 4; j++) {
        const int n = n0 + tx * 4 + j;
        const float bias = (MODE == 0) ? (b1[n] + b2[n]) : b1[n];
#pragma unroll
        for (int i = 0; i < 8; i++) {
            const int m = m0 + ty * 8 + i;
            const float v = acc[i][j] + bias;
            if (MODE == 0) {
                const int bb = m >> 9;      // m = b*512 + s
                const int ss = m & 511;
                g_xi[(ss * BB + bb) * HH + n] = v;
            } else {
                const int ss = m >> 6;      // m = s*64 + b
                const int bb = m & 63;
                C[(bb * SS + ss) * OO + n] = v;
            }
        }
    }
}

// ---------------------------------------------------------------------------
// Persistent recurrence kernel: 128 CTAs x 128 threads, 1 CTA/SM.
// CTA (bt, jt) owns b in [bt*32, bt*32+32), j in [jt*16, jt*16+16).
// Wh slice (16x1024) pinned in SMEM for all 512 steps; h staged per step.
// Grid barrier: monotonic counter (reset by reset_bar_kernel each launch).
// ---------------------------------------------------------------------------
#define WH_STRIDE 1028           // pad: conflict-free float4 row loads
#define HS_STRIDE 33             // transposed h, conflict-free scalar loads
#define SMEM_FLOATS (16 * WH_STRIDE + 1024 * HS_STRIDE)
#define SMEM_BYTES  (SMEM_FLOATS * 4)

__global__ __launch_bounds__(128)
void rnn_persistent_kernel(const float* __restrict__ Wh)
{
    extern __shared__ float sm[];
    float* Wh_s = sm;                     // [16][1028]
    float* h_s  = sm + 16 * WH_STRIDE;    // [1024][33] (k-major, transposed)

    const int tid = threadIdx.x;
    const int jt = blockIdx.x & 63;
    const int bt = blockIdx.x >> 6;
    const int j0 = jt * 16;
    const int b0 = bt * 32;

    // Load Wh slice once (stays resident for all 512 steps)
    for (int idx = tid; idx < 16 * 256; idx += 128) {
        const int rr = idx >> 8;
        const int cc = (idx & 255) * 4;
        float4 v = *(const float4*)&Wh[(j0 + rr) * HH + cc];
        *(float4*)&Wh_s[rr * WH_STRIDE + cc] = v;
    }

    const int bx  = tid & 15;
    const int jp  = tid >> 4;
    const int bl0 = 2 * bx, bl1 = bl0 + 1;
    const int jl0 = 2 * jp, jl1 = jl0 + 1;
    const int bg0 = b0 + bl0;
    const int jg0 = j0 + jl0;

    __syncthreads();

    for (int t = 0; t < SS; t++) {
        float acc00 = 0.f, acc01 = 0.f, acc10 = 0.f, acc11 = 0.f;

        if (t > 0) {
            // Stage h(t-1) for our 32 batches into transposed SMEM
            const float* hsrc = g_hs + (size_t)(t - 1) * BB * HH + (size_t)b0 * HH;
            for (int idx = tid; idx < 32 * 256; idx += 128) {
                const int bb = idx >> 8;
                const int cc = (idx & 255) * 4;
                float4 v = *(const float4*)&hsrc[bb * HH + cc];
                h_s[(cc + 0) * HS_STRIDE + bb] = v.x;
                h_s[(cc + 1) * HS_STRIDE + bb] = v.y;
                h_s[(cc + 2) * HS_STRIDE + bb] = v.z;
                h_s[(cc + 3) * HS_STRIDE + bb] = v.w;
            }
            __syncthreads();

#pragma unroll 4
            for (int k = 0; k < HH; k += 4) {
                float4 w0 = *(const float4*)&Wh_s[jl0 * WH_STRIDE + k];
                float4 w1 = *(const float4*)&Wh_s[jl1 * WH_STRIDE + k];
                float a00 = h_s[(k + 0) * HS_STRIDE + bl0];
                float a01 = h_s[(k + 1) * HS_STRIDE + bl0];
                float a02 = h_s[(k + 2) * HS_STRIDE + bl0];
                float a03 = h_s[(k + 3) * HS_STRIDE + bl0];
                float a10 = h_s[(k + 0) * HS_STRIDE + bl1];
                float a11 = h_s[(k + 1) * HS_STRIDE + bl1];
                float a12 = h_s[(k + 2) * HS_STRIDE + bl1];
                float a13 = h_s[(k + 3) * HS_STRIDE + bl1];
                acc00 += a00 * w0.x; acc00 += a01 * w0.y; acc00 += a02 * w0.z; acc00 += a03 * w0.w;
                acc01 += a00 * w1.x; acc01 += a01 * w1.y; acc01 += a02 * w1.z; acc01 += a03 * w1.w;
                acc10 += a10 * w0.x; acc10 += a11 * w0.y; acc10 += a12 * w0.z; acc10 += a13 * w0.w;
                acc11 += a10 * w1.x; acc11 += a11 * w1.y; acc11 += a12 * w1.z; acc11 += a13 * w1.w;
            }
        }

        // Epilogue: h_new = tanh(xi + acc), store to g_hs[t]
        const float* xit = g_xi + (size_t)t * BB * HH;
        float* hdst = g_hs + (size_t)t * BB * HH;
        const int i00 = bg0 * HH + jg0;
        const int i10 = (bg0 + 1) * HH + jg0;
        float x00 = xit[i00], x01 = xit[i00 + 1];
        float x10 = xit[i10], x11 = xit[i10 + 1];
        hdst[i00]     = tanhf(acc00 + x00);
        hdst[i00 + 1] = tanhf(acc01 + x01);
        hdst[i10]     = tanhf(acc10 + x10);
        hdst[i10 + 1] = tanhf(acc11 + x11);

        if (t < SS - 1) {
            __threadfence();          // publish our h writes (gpu scope)
            __syncthreads();          // all threads in CTA done
            if (tid == 0) {
                atomicAdd(&g_bar, 1u);
                const unsigned target = (unsigned)(t + 1) * NBLK;
                while (*((volatile unsigned*)&g_bar) < target) { }
                __threadfence();      // acquire before CTA proceeds
            }
            __syncthreads();
        }
    }
}

__global__ void copy_hlast_kernel(float* __restrict__ dst)
{
    const int i = blockIdx.x * blockDim.x + threadIdx.x;
    dst[i] = g_hs[(size_t)(SS - 1) * BB * HH + i];
}

// ---------------------------------------------------------------------------
extern "C" void kernel_launch(void* const* d_in, const int* in_sizes, int n_in,
                              void* d_out, int out_size)
{
    const float* x  = (const float*)d_in[0];
    const float* Wi = (const float*)d_in[1];
    const float* bi = (const float*)d_in[2];
    const float* Wh = (const float*)d_in[3];
    const float* bh = (const float*)d_in[4];
    const float* Wo = (const float*)d_in[5];
    const float* bo = (const float*)d_in[6];
    float* out = (float*)d_out;

    cudaFuncSetAttribute(rnn_persistent_kernel,
                         cudaFuncAttributeMaxDynamicSharedMemorySize, SMEM_BYTES);

    // 1) xi = x @ Wi^T + bi + bh  (writes g_xi[s][b][h])
    dim3 g1((SS * BB) / 128, HH / 64);
    gemm_nt_kernel<0><<<g1, 256>>>(x, Wi, bi, bh, nullptr, II);

    // 2) recurrence (persistent, grid-barriered)
    reset_bar_kernel<<<1, 1>>>();
    rnn_persistent_kernel<<<NBLK, 128, SMEM_BYTES>>>(Wh);

    // 3) out = hs @ Wo^T + bo  (reads g_hs, writes d_out[b][s][o])
    dim3 g2((SS * BB) / 128, OO / 64);
    gemm_nt_kernel<1><<<g2, 256>>>(nullptr, Wo, bo, nullptr, out, HH);

    // 4) h_last appended after outputs if the harness expects it
    if (out_size >= BB * SS * OO + BB * HH) {
        copy_hlast_kernel<<<(BB * HH) / 256, 256>>>(out + (size_t)BB * SS * OO);
    }
}

// round 2
// speedup vs baseline: 1.6020x; 1.6020x over previous
#include <cuda_runtime.h>
#include <math.h>

// Problem dims
#define BB 64
#define SS 512
#define II 512
#define HH 1024
#define OO 512
#define NBLK 128   // persistent grid (<=148 SMs, 1 CTA/SM => co-resident)

// Scratch
__device__ float g_xi[SS * BB * HH];   // [s][b][h] : x@Wi^T + bi + bh
__device__ float g_hs[SS * BB * HH];   // [s][b][h] : hidden states
__device__ unsigned g_flags[NBLK * 32]; // per-CTA step flags (128B apart)

__global__ void reset_flags_kernel() { g_flags[threadIdx.x * 32] = 0u; }

// ---------------------------------------------------------------------------
// Tiled fp32 GEMM, C = A(MxK) * Bw(NxK)^T + bias, NT layout.
// MODE 0: A = x, write g_xi[s][b][n], m = b*SS+s, bias = bi[n]+bh[n]
// MODE 1: A = g_hs, write C[b][s][n], m = s*BB+b, bias = b1[n]
// ---------------------------------------------------------------------------
template <int MODE>
__global__ __launch_bounds__(256)
void gemm_nt_kernel(const float* __restrict__ A, const float* __restrict__ Bw,
                    const float* __restrict__ b1, const float* __restrict__ b2,
                    float* __restrict__ C, int K)
{
    __shared__ float As[16 * 132];
    __shared__ float Bs[16 * 68];

    const int tid = threadIdx.x;
    const int m0 = blockIdx.x * 128;
    const int n0 = blockIdx.y * 64;
    const int tx = tid & 15;
    const int ty = tid >> 4;
    const int r  = tid >> 2;
    const int c4 = (tid & 3) * 4;

    const float* Abase = (MODE == 0) ? A : (const float*)g_hs;

    float acc[8][4];
#pragma unroll
    for (int i = 0; i < 8; i++)
#pragma unroll
        for (int j = 0; j < 4; j++) acc[i][j] = 0.f;

    const float* Ap0 = Abase + (size_t)(m0 + r) * K + c4;
    const float* Ap1 = Abase + (size_t)(m0 + r + 64) * K + c4;
    const float* Bp  = Bw    + (size_t)(n0 + r) * K + c4;

    for (int k0 = 0; k0 < K; k0 += 16) {
        float4 av0 = *(const float4*)(Ap0 + k0);
        float4 av1 = *(const float4*)(Ap1 + k0);
        float4 bv  = *(const float4*)(Bp  + k0);
        __syncthreads();
        As[(c4 + 0) * 132 + r] = av0.x;
        As[(c4 + 1) * 132 + r] = av0.y;
        As[(c4 + 2) * 132 + r] = av0.z;
        As[(c4 + 3) * 132 + r] = av0.w;
        As[(c4 + 0) * 132 + r + 64] = av1.x;
        As[(c4 + 1) * 132 + r + 64] = av1.y;
        As[(c4 + 2) * 132 + r + 64] = av1.z;
        As[(c4 + 3) * 132 + r + 64] = av1.w;
        Bs[(c4 + 0) * 68 + r] = bv.x;
        Bs[(c4 + 1) * 68 + r] = bv.y;
        Bs[(c4 + 2) * 68 + r] = bv.z;
        Bs[(c4 + 3) * 68 + r] = bv.w;
        __syncthreads();
#pragma unroll
        for (int kk = 0; kk < 16; kk++) {
            float4 a0 = *(const float4*)&As[kk * 132 + ty * 8];
            float4 a1 = *(const float4*)&As[kk * 132 + ty * 8 + 4];
            float4 b  = *(const float4*)&Bs[kk * 68 + tx * 4];
            float am[8] = {a0.x, a0.y, a0.z, a0.w, a1.x, a1.y, a1.z, a1.w};
            float bn[4] = {b.x, b.y, b.z, b.w};
#pragma unroll
            for (int i = 0; i < 8; i++)
#pragma unroll
                for (int j = 0; j < 4; j++) acc[i][j] += am[i] * bn[j];
        }
    }

#pragma unroll
    for (int j = 0; j < 4; j++) {
        const int n = n0 + tx * 4 + j;
        const float bias = (MODE == 0) ? (b1[n] + b2[n]) : b1[n];
#pragma unroll
        for (int i = 0; i < 8; i++) {
            const int m = m0 + ty * 8 + i;
            const float v = acc[i][j] + bias;
            if (MODE == 0) {
                const int bb = m >> 9;
                const int ss = m & 511;
                g_xi[(ss * BB + bb) * HH + n] = v;
            } else {
                const int ss = m >> 6;
                const int bb = m & 63;
                C[(bb * SS + ss) * OO + n] = v;
            }
        }
    }
}

// ---------------------------------------------------------------------------
// Persistent recurrence: 128 CTAs x 256 threads (2 warps/SMSP), 1 CTA/SM.
// CTA (bt, jt): b in [bt*16, +16), j in [jt*32, +32).
// k-split across thread halves: kh=0 -> k[0,512), kh=1 -> k[512,1024),
// combined via SMEM reduction. Wh pinned in SMEM (k-major, stride 34,
// conflict-free float2 loads). h staged row-major (broadcast reads).
// ---------------------------------------------------------------------------
#define WST 34                         // Wh_s k-row stride (floats)
#define SM_WH  (1024 * WST)            // 34816 floats
#define SM_H   (16 * 1024)             // 16384 floats
#define SM_RED (128 * 4)               // 512 floats
#define SMEM_FLOATS (SM_WH + SM_H + SM_RED)
#define SMEM_BYTES  (SMEM_FLOATS * 4)  // 206848 B

__global__ __launch_bounds__(256, 1)
void rnn_persistent_kernel(const float* __restrict__ Wh)
{
    extern __shared__ float sm[];
    float* Wh_s = sm;                   // [k][j], stride WST
    float* h_s  = sm + SM_WH;           // [b][k], stride 1024
    float* red  = sm + SM_WH + SM_H;    // [128][4]

    const int tid = threadIdx.x;
    const int cta = blockIdx.x;
    const int jt = cta & 31;            // 32 j-tiles
    const int bt = cta >> 5;            // 4 b-tiles
    const int j0 = jt * 32;
    const int b0 = bt * 16;

    const int kh   = tid >> 7;          // k-half
    const int wtid = tid & 127;
    const int tx = wtid & 15;           // j-group (2 j each)
    const int ty = wtid >> 4;           // b-group (2 b each)
    const int kbeg = kh * 512;
    const int bl0 = 2 * ty, bl1 = bl0 + 1;
    const int jl  = 2 * tx;
    const int bg0 = b0 + bl0;
    const int jg  = j0 + jl;

    // Pin Wh slice [j0..j0+32) in SMEM, k-major (once per launch)
    for (int idx = tid; idx < 32 * 1024; idx += 256) {
        const int j = idx >> 10;
        const int k = idx & 1023;
        Wh_s[k * WST + j] = Wh[(j0 + j) * HH + k];
    }
    __syncthreads();

    for (int t = 0; t < SS; t++) {
        // Prefetch xi early (independent of barrier / h)
        const float* xit = g_xi + (size_t)t * BB * HH;
        float2 x0 = make_float2(0.f, 0.f), x1 = make_float2(0.f, 0.f);
        if (kh == 0) {
            x0 = *(const float2*)&xit[bg0 * HH + jg];
            x1 = *(const float2*)&xit[(bg0 + 1) * HH + jg];
        }

        float acc00 = 0.f, acc01 = 0.f, acc10 = 0.f, acc11 = 0.f;

        if (t > 0) {
            // Grid barrier: each of 128 threads polls one CTA's flag
            if (tid < NBLK) {
                while (*(volatile unsigned*)&g_flags[tid * 32] < (unsigned)t) {}
            }
            __syncthreads();
            __threadfence();   // acquire: order flag-read before h reads

            // Stage h(t-1)[b0..b0+16) row-major (L2-fresh)
            const float4* hsrc = (const float4*)(g_hs + (size_t)(t - 1) * BB * HH
                                                      + (size_t)b0 * HH);
            float4* hdst4 = (float4*)h_s;
#pragma unroll
            for (int it = 0; it < 16; it++) {
                hdst4[tid + it * 256] = __ldcg(&hsrc[tid + it * 256]);
            }
            __syncthreads();

            // Half-K GEMM: 2b x 2j per thread
#pragma unroll 8
            for (int k = kbeg; k < kbeg + 512; k += 4) {
                float4 a0 = *(const float4*)&h_s[bl0 * 1024 + k];
                float4 a1 = *(const float4*)&h_s[bl1 * 1024 + k];
                float2 w0 = *(const float2*)&Wh_s[(k + 0) * WST + jl];
                float2 w1 = *(const float2*)&Wh_s[(k + 1) * WST + jl];
                float2 w2 = *(const float2*)&Wh_s[(k + 2) * WST + jl];
                float2 w3 = *(const float2*)&Wh_s[(k + 3) * WST + jl];
                acc00 += a0.x * w0.x; acc01 += a0.x * w0.y;
                acc10 += a1.x * w0.x; acc11 += a1.x * w0.y;
                acc00 += a0.y * w1.x; acc01 += a0.y * w1.y;
                acc10 += a1.y * w1.x; acc11 += a1.y * w1.y;
                acc00 += a0.z * w2.x; acc01 += a0.z * w2.y;
                acc10 += a1.z * w2.x; acc11 += a1.z * w2.y;
                acc00 += a0.w * w3.x; acc01 += a0.w * w3.y;
                acc10 += a1.w * w3.x; acc11 += a1.w * w3.y;
            }
        }

        // Combine k-halves
        if (kh == 1) {
            *(float4*)&red[wtid * 4] = make_float4(acc00, acc01, acc10, acc11);
        }
        __syncthreads();
        if (kh == 0) {
            const float4 r = *(const float4*)&red[wtid * 4];
            const float h00 = tanhf(acc00 + r.x + x0.x);
            const float h01 = tanhf(acc01 + r.y + x0.y);
            const float h10 = tanhf(acc10 + r.z + x1.x);
            const float h11 = tanhf(acc11 + r.w + x1.y);
            float* hdst = g_hs + (size_t)t * BB * HH;
            *(float2*)&hdst[bg0 * HH + jg]       = make_float2(h00, h01);
            *(float2*)&hdst[(bg0 + 1) * HH + jg] = make_float2(h10, h11);
        }

        if (t < SS - 1) {
            __threadfence();   // publish h(t) before flag
            __syncthreads();
            if (tid == 0) {
                atomicExch((unsigned*)&g_flags[cta * 32], (unsigned)(t + 1));
            }
        }
    }
}

__global__ void copy_hlast_kernel(float* __restrict__ dst)
{
    const int i = blockIdx.x * blockDim.x + threadIdx.x;
    dst[i] = g_hs[(size_t)(SS - 1) * BB * HH + i];
}

// ---------------------------------------------------------------------------
extern "C" void kernel_launch(void* const* d_in, const int* in_sizes, int n_in,
                              void* d_out, int out_size)
{
    const float* x  = (const float*)d_in[0];
    const float* Wi = (const float*)d_in[1];
    const float* bi = (const float*)d_in[2];
    const float* Wh = (const float*)d_in[3];
    const float* bh = (const float*)d_in[4];
    const float* Wo = (const float*)d_in[5];
    const float* bo = (const float*)d_in[6];
    float* out = (float*)d_out;

    cudaFuncSetAttribute(rnn_persistent_kernel,
                         cudaFuncAttributeMaxDynamicSharedMemorySize, SMEM_BYTES);

    // 1) xi = x @ Wi^T + bi + bh
    dim3 g1((SS * BB) / 128, HH / 64);
    gemm_nt_kernel<0><<<g1, 256>>>(x, Wi, bi, bh, nullptr, II);

    // 2) recurrence
    reset_flags_kernel<<<1, NBLK>>>();
    rnn_persistent_kernel<<<NBLK, 256, SMEM_BYTES>>>(Wh);

    // 3) out = hs @ Wo^T + bo
    dim3 g2((SS * BB) / 128, OO / 64);
    gemm_nt_kernel<1><<<g2, 256>>>(nullptr, Wo, bo, nullptr, out, HH);

    // 4) h_last appended after outputs if expected
    if (out_size >= BB * SS * OO + BB * HH) {
        copy_hlast_kernel<<<(BB * HH) / 256, 256>>>(out + (size_t)BB * SS * OO);
    }
}

// round 4
// speedup vs baseline: 2.6565x; 1.6583x over previous
#include <cuda_runtime.h>
#include <cuda_bf16.h>
#include <math.h>
#include <stdint.h>

// Problem dims
#define BB 64
#define SS 512
#define II 512
#define HH 1024
#define OO 512
#define NBLK 128

// Scratch
__device__ float g_xi[SS * BB * HH];   // [s][b][h]
__device__ float g_hs[SS * BB * HH];   // [s][b][h]
__device__ unsigned g_flags[NBLK * 32];

__global__ void reset_flags_kernel() { g_flags[threadIdx.x * 32] = 0u; }

// ---------------------------------------------------------------------------
// fp32 GEMM (unchanged)
// ---------------------------------------------------------------------------
template <int MODE>
__global__ __launch_bounds__(256)
void gemm_nt_kernel(const float* __restrict__ A, const float* __restrict__ Bw,
                    const float* __restrict__ b1, const float* __restrict__ b2,
                    float* __restrict__ C, int K)
{
    __shared__ float As[16 * 132];
    __shared__ float Bs[16 * 68];

    const int tid = threadIdx.x;
    const int m0 = blockIdx.x * 128;
    const int n0 = blockIdx.y * 64;
    const int tx = tid & 15;
    const int ty = tid >> 4;
    const int r  = tid >> 2;
    const int c4 = (tid & 3) * 4;

    const float* Abase = (MODE == 0) ? A : (const float*)g_hs;

    float acc[8][4];
#pragma unroll
    for (int i = 0; i < 8; i++)
#pragma unroll
        for (int j = 0; j < 4; j++) acc[i][j] = 0.f;

    const float* Ap0 = Abase + (size_t)(m0 + r) * K + c4;
    const float* Ap1 = Abase + (size_t)(m0 + r + 64) * K + c4;
    const float* Bp  = Bw    + (size_t)(n0 + r) * K + c4;

    for (int k0 = 0; k0 < K; k0 += 16) {
        float4 av0 = *(const float4*)(Ap0 + k0);
        float4 av1 = *(const float4*)(Ap1 + k0);
        float4 bv  = *(const float4*)(Bp  + k0);
        __syncthreads();
        As[(c4 + 0) * 132 + r] = av0.x;
        As[(c4 + 1) * 132 + r] = av0.y;
        As[(c4 + 2) * 132 + r] = av0.z;
        As[(c4 + 3) * 132 + r] = av0.w;
        As[(c4 + 0) * 132 + r + 64] = av1.x;
        As[(c4 + 1) * 132 + r + 64] = av1.y;
        As[(c4 + 2) * 132 + r + 64] = av1.z;
        As[(c4 + 3) * 132 + r + 64] = av1.w;
        Bs[(c4 + 0) * 68 + r] = bv.x;
        Bs[(c4 + 1) * 68 + r] = bv.y;
        Bs[(c4 + 2) * 68 + r] = bv.z;
        Bs[(c4 + 3) * 68 + r] = bv.w;
        __syncthreads();
#pragma unroll
        for (int kk = 0; kk < 16; kk++) {
            float4 a0 = *(const float4*)&As[kk * 132 + ty * 8];
            float4 a1 = *(const float4*)&As[kk * 132 + ty * 8 + 4];
            float4 b  = *(const float4*)&Bs[kk * 68 + tx * 4];
            float am[8] = {a0.x, a0.y, a0.z, a0.w, a1.x, a1.y, a1.z, a1.w};
            float bn[4] = {b.x, b.y, b.z, b.w};
#pragma unroll
            for (int i = 0; i < 8; i++)
#pragma unroll
                for (int j = 0; j < 4; j++) acc[i][j] += am[i] * bn[j];
        }
    }

#pragma unroll
    for (int j = 0; j < 4; j++) {
        const int n = n0 + tx * 4 + j;
        const float bias = (MODE == 0) ? (b1[n] + b2[n]) : b1[n];
#pragma unroll
        for (int i = 0; i < 8; i++) {
            const int m = m0 + ty * 8 + i;
            const float v = acc[i][j] + bias;
            if (MODE == 0) {
                const int bb = m >> 9;
                const int ss = m & 511;
                g_xi[(ss * BB + bb) * HH + n] = v;
            } else {
                const int ss = m >> 6;
                const int bb = m & 63;
                C[(bb * SS + ss) * OO + n] = v;
            }
        }
    }
}

// ---------------------------------------------------------------------------
// mma.sync helpers (base PTX, works on compute_103)
// ---------------------------------------------------------------------------
__device__ __forceinline__ void mma16816(float d[4], const uint32_t a[4],
                                         const uint32_t b[2])
{
    asm volatile(
        "mma.sync.aligned.m16n8k16.row.col.f32.bf16.bf16.f32 "
        "{%0,%1,%2,%3}, {%4,%5,%6,%7}, {%8,%9}, {%0,%1,%2,%3};"
        : "+f"(d[0]), "+f"(d[1]), "+f"(d[2]), "+f"(d[3])
        : "r"(a[0]), "r"(a[1]), "r"(a[2]), "r"(a[3]), "r"(b[0]), "r"(b[1]));
}

__device__ __forceinline__ uint32_t pack_bf16(float f0, float f1)
{
    __nv_bfloat162 v;
    v.x = __float2bfloat16(f0);
    v.y = __float2bfloat16(f1);
    return *(uint32_t*)&v;
}

// ---------------------------------------------------------------------------
// Persistent recurrence via mma.sync bf16x3 split.
// 128 CTAs x 256 threads (8 warps). CTA (bt,jt): b in [bt*8,+8), j in [jt*64,+64).
// Warp w owns k-slice [w*128,(w+1)*128); computes full 64j x 8b partial.
// Wh_hi: register A-fragments (loaded once). Wh_lo: SMEM (swizzled).
// h_hi/h_lo: staged per step from fp32 g_hs into swizzled SMEM.
// Cross-warp k-reduction in SMEM, then xi + tanh epilogue.
// ---------------------------------------------------------------------------
#define OFF_WHL 0                      // 64 rows x 2048 B = 128 KB
#define OFF_HH  131072                 // 8 rows x 2048 B = 16 KB
#define OFF_HL  147456                 // 16 KB
#define OFF_RED 163840                 // 8 x 512 floats = 16 KB
#define RNN_SMEM_BYTES 180224

// swizzled byte offset within a [row][1024k] bf16 slab (2048 B rows)
__device__ __forceinline__ int swz(int row, int kbyte) {
    return row * 2048 + (kbyte ^ ((row & 7) << 4));
}

__global__ __launch_bounds__(256, 1)
void rnn_persistent_kernel(const float* __restrict__ Wh)
{
    extern __shared__ char sm[];
    float* red = (float*)(sm + OFF_RED);

    const int tid = threadIdx.x;
    const int wid = tid >> 5;
    const int lane = tid & 31;
    const int g = lane >> 2;        // group id (row / b-col)
    const int tig = lane & 3;       // thread in group
    const int cta = blockIdx.x;
    const int jt = cta & 15;
    const int bt = cta >> 4;
    const int j0 = jt * 64;
    const int b0 = bt * 8;
    const int kw0 = wid * 128;      // this warp's k-slice base

    // ---- one-time: load Wh_hi A-fragments to regs; write Wh_lo to SMEM ----
    uint32_t a_hi[4][8][4];
#pragma unroll
    for (int mt = 0; mt < 4; mt++) {
#pragma unroll
        for (int ks = 0; ks < 8; ks++) {
#pragma unroll
            for (int r = 0; r < 4; r++) {
                const int jl = mt * 16 + g + ((r & 1) ? 8 : 0);
                const int k  = kw0 + ks * 16 + tig * 2 + ((r & 2) ? 8 : 0);
                const float2 w = *(const float2*)&Wh[(size_t)(j0 + jl) * HH + k];
                const uint32_t hi = pack_bf16(w.x, w.y);
                a_hi[mt][ks][r] = hi;
                const __nv_bfloat162 h2 = *(const __nv_bfloat162*)&hi;
                const uint32_t lo = pack_bf16(w.x - __bfloat162float(h2.x),
                                              w.y - __bfloat162float(h2.y));
                *(uint32_t*)(sm + OFF_WHL + swz(jl, k * 2)) = lo;
            }
        }
    }
    __syncthreads();

    for (int t = 0; t < SS; t++) {
        // prefetch xi for our 2 output elements (e = 2*tid, 2*tid+1)
        const int eb = tid >> 5;            // b-local  (e>>6 with e=2*tid)
        const int ej = (tid & 31) * 2;      // j-local
        const float2 xiv = *(const float2*)
            &g_xi[(size_t)t * BB * HH + (size_t)(b0 + eb) * HH + j0 + ej];

        float h0, h1;
        if (t > 0) {
            // grid barrier
            if (tid < NBLK) {
                while (*(volatile unsigned*)&g_flags[tid * 32] < (unsigned)t) {}
            }
            __syncthreads();
            __threadfence();

            // stage h(t-1): fp32 -> (hi,lo) bf16 swizzled SMEM
            const float* hsrc = g_hs + (size_t)(t - 1) * BB * HH + (size_t)b0 * HH;
#pragma unroll
            for (int it = 0; it < 8; it++) {
                const int u = it * 256 + tid;      // float4 unit, 2048 total
                const int b = u >> 8;
                const int k = (u & 255) * 4;
                const float4 v = __ldcg((const float4*)(hsrc + b * HH + k));
                uint2 vh, vl;
                vh.x = pack_bf16(v.x, v.y);
                vh.y = pack_bf16(v.z, v.w);
                const __nv_bfloat162 p0 = *(const __nv_bfloat162*)&vh.x;
                const __nv_bfloat162 p1 = *(const __nv_bfloat162*)&vh.y;
                vl.x = pack_bf16(v.x - __bfloat162float(p0.x),
                                 v.y - __bfloat162float(p0.y));
                vl.y = pack_bf16(v.z - __bfloat162float(p1.x),
                                 v.w - __bfloat162float(p1.y));
                const int off = swz(b, k * 2);
                *(uint2*)(sm + OFF_HH + off) = vh;
                *(uint2*)(sm + OFF_HL + off) = vl;
            }
            __syncthreads();

            // ---- tensor-core mainloop ----
            float acc[4][4];
#pragma unroll
            for (int mt = 0; mt < 4; mt++)
#pragma unroll
                for (int r = 0; r < 4; r++) acc[mt][r] = 0.f;

#pragma unroll
            for (int ks = 0; ks < 8; ks++) {
                const int kb = kw0 + ks * 16;
                const int kc = kb + tig * 2;
                uint32_t bh[2], bl[2];
                bh[0] = *(const uint32_t*)(sm + OFF_HH + swz(g, kc * 2));
                bh[1] = *(const uint32_t*)(sm + OFF_HH + swz(g, (kc + 8) * 2));
                bl[0] = *(const uint32_t*)(sm + OFF_HL + swz(g, kc * 2));
                bl[1] = *(const uint32_t*)(sm + OFF_HL + swz(g, (kc + 8) * 2));
#pragma unroll
                for (int mt = 0; mt < 4; mt++)
                    mma16816(acc[mt], a_hi[mt][ks], bh);
#pragma unroll
                for (int mt = 0; mt < 4; mt++)
                    mma16816(acc[mt], a_hi[mt][ks], bl);
#pragma unroll
                for (int mt = 0; mt < 4; mt++) {
                    uint32_t al[4];
#pragma unroll
                    for (int r = 0; r < 4; r++) {
                        const int jl = mt * 16 + g + ((r & 1) ? 8 : 0);
                        const int k  = kc + ((r & 2) ? 8 : 0);
                        al[r] = *(const uint32_t*)(sm + OFF_WHL + swz(jl, k * 2));
                    }
                    mma16816(acc[mt], al, bh);
                }
            }

            // ---- cross-warp reduction ----
            float* rw = red + wid * 512;    // [b][j] : b*64 + j
#pragma unroll
            for (int mt = 0; mt < 4; mt++) {
                const int jl = mt * 16 + g;
                rw[(tig * 2) * 64 + jl]         = acc[mt][0];
                rw[(tig * 2 + 1) * 64 + jl]     = acc[mt][1];
                rw[(tig * 2) * 64 + jl + 8]     = acc[mt][2];
                rw[(tig * 2 + 1) * 64 + jl + 8] = acc[mt][3];
            }
            __syncthreads();

            const int e = tid * 2;
            float s0 = 0.f, s1 = 0.f;
#pragma unroll
            for (int w = 0; w < 8; w++) {
                s0 += red[w * 512 + e];
                s1 += red[w * 512 + e + 1];
            }
            h0 = tanhf(s0 + xiv.x);
            h1 = tanhf(s1 + xiv.y);
        } else {
            h0 = tanhf(xiv.x);
            h1 = tanhf(xiv.y);
        }

        *(float2*)&g_hs[(size_t)t * BB * HH + (size_t)(b0 + eb) * HH + j0 + ej]
            = make_float2(h0, h1);

        if (t < SS - 1) {
            __threadfence();
            __syncthreads();
            if (tid == 0) {
                atomicExch((unsigned*)&g_flags[cta * 32], (unsigned)(t + 1));
            }
        }
    }
}

__global__ void copy_hlast_kernel(float* __restrict__ dst)
{
    const int i = blockIdx.x * blockDim.x + threadIdx.x;
    dst[i] = g_hs[(size_t)(SS - 1) * BB * HH + i];
}

// ---------------------------------------------------------------------------
extern "C" void kernel_launch(void* const* d_in, const int* in_sizes, int n_in,
                              void* d_out, int out_size)
{
    const float* x  = (const float*)d_in[0];
    const float* Wi = (const float*)d_in[1];
    const float* bi = (const float*)d_in[2];
    const float* Wh = (const float*)d_in[3];
    const float* bh = (const float*)d_in[4];
    const float* Wo = (const float*)d_in[5];
    const float* bo = (const float*)d_in[6];
    float* out = (float*)d_out;

    cudaFuncSetAttribute(rnn_persistent_kernel,
                         cudaFuncAttributeMaxDynamicSharedMemorySize, RNN_SMEM_BYTES);

    dim3 g1((SS * BB) / 128, HH / 64);
    gemm_nt_kernel<0><<<g1, 256>>>(x, Wi, bi, bh, nullptr, II);

    reset_flags_kernel<<<1, NBLK>>>();
    rnn_persistent_kernel<<<NBLK, 256, RNN_SMEM_BYTES>>>(Wh);

    dim3 g2((SS * BB) / 128, OO / 64);
    gemm_nt_kernel<1><<<g2, 256>>>(nullptr, Wo, bo, nullptr, out, HH);

    if (out_size >= BB * SS * OO + BB * HH) {
        copy_hlast_kernel<<<(BB * HH) / 256, 256>>>(out + (size_t)BB * SS * OO);
    }
}

// round 5
// speedup vs baseline: 3.6876x; 1.3882x over previous
#include <cuda_runtime.h>
#include <cuda_bf16.h>
#include <math.h>
#include <stdint.h>

// Problem dims
#define BB 64
#define SS 512
#define II 512
#define HH 1024
#define OO 512
#define NBLK 128

// Scratch (device globals; no allocations)
__device__ float g_xi[SS * BB * HH];               // [s][b][h]
__device__ float g_hs[SS * BB * HH];               // [s][b][h] fp32
__device__ __nv_bfloat16 g_hshi[SS * BB * HH];     // hs split hi
__device__ __nv_bfloat16 g_hslo[SS * BB * HH];     // hs split lo
__device__ __nv_bfloat16 g_xhi[BB * SS * II];
__device__ __nv_bfloat16 g_xlo[BB * SS * II];
__device__ __nv_bfloat16 g_Wihi[HH * II];
__device__ __nv_bfloat16 g_Wilo[HH * II];
__device__ __nv_bfloat16 g_Wohi[OO * HH];
__device__ __nv_bfloat16 g_Wolo[OO * HH];
__device__ unsigned g_flags[NBLK * 32];

__global__ void reset_flags_kernel() { g_flags[threadIdx.x * 32] = 0u; }

// ---------------------------------------------------------------------------
// helpers
// ---------------------------------------------------------------------------
__device__ __forceinline__ uint32_t smem_u32(const void* p) {
    return (uint32_t)__cvta_generic_to_shared(p);
}
__device__ __forceinline__ void mma16816(float d[4], const uint32_t a[4],
                                         const uint32_t b[2])
{
    asm volatile(
        "mma.sync.aligned.m16n8k16.row.col.f32.bf16.bf16.f32 "
        "{%0,%1,%2,%3}, {%4,%5,%6,%7}, {%8,%9}, {%0,%1,%2,%3};"
        : "+f"(d[0]), "+f"(d[1]), "+f"(d[2]), "+f"(d[3])
        : "r"(a[0]), "r"(a[1]), "r"(a[2]), "r"(a[3]), "r"(b[0]), "r"(b[1]));
}
__device__ __forceinline__ uint32_t pack_bf16(float f0, float f1)
{
    __nv_bfloat162 v;
    v.x = __float2bfloat16(f0);
    v.y = __float2bfloat16(f1);
    return *(uint32_t*)&v;
}

// ---------------------------------------------------------------------------
// fp32 -> (hi,lo) bf16 split kernels. WHICH: 0=x, 1=Wi, 2=Wo
// ---------------------------------------------------------------------------
template <int WHICH>
__global__ void split_kernel(const float* __restrict__ src)
{
    __nv_bfloat16* hi = (WHICH == 0) ? g_xhi : (WHICH == 1) ? g_Wihi : g_Wohi;
    __nv_bfloat16* lo = (WHICH == 0) ? g_xlo : (WHICH == 1) ? g_Wilo : g_Wolo;
    const int i = (blockIdx.x * blockDim.x + threadIdx.x) * 4;
    const float4 v = *(const float4*)(src + i);
    uint2 h, l;
    h.x = pack_bf16(v.x, v.y);
    h.y = pack_bf16(v.z, v.w);
    const __nv_bfloat162 p0 = *(const __nv_bfloat162*)&h.x;
    const __nv_bfloat162 p1 = *(const __nv_bfloat162*)&h.y;
    l.x = pack_bf16(v.x - __bfloat162float(p0.x), v.y - __bfloat162float(p0.y));
    l.y = pack_bf16(v.z - __bfloat162float(p1.x), v.w - __bfloat162float(p1.y));
    *(uint2*)(hi + i) = h;
    *(uint2*)(lo + i) = l;
}

// ---------------------------------------------------------------------------
// Tensor-core bf16x3 GEMM: C = A(MxK) * B(NxK)^T + bias  (fp32 accum)
// MODE 0: A = x split, B = Wi split, write g_xi[s][b][n], m=b*512+s,
//         bias = b1[n]+b2[n]
// MODE 1: A = hs split, B = Wo split, write C[b][s][n], m=s*64+b, bias=b1[n]
// Tile 128x128x64, 8 warps (warp 32m x 64n), cp.async double buffer.
// ---------------------------------------------------------------------------
#define GOFF_AH(st) ((st) * 65536 + 0)
#define GOFF_AL(st) ((st) * 65536 + 16384)
#define GOFF_BH(st) ((st) * 65536 + 32768)
#define GOFF_BL(st) ((st) * 65536 + 49152)
#define GEMM_SMEM 131072

__device__ __forceinline__ int swzg(int row, int kb) {
    return row * 128 + (kb ^ ((row & 7) << 4));
}

template <int MODE>
__global__ __launch_bounds__(256, 1)
void gemm_tc_kernel(const float* __restrict__ b1, const float* __restrict__ b2,
                    float* __restrict__ C, int K)
{
    extern __shared__ char smg[];
    const uint32_t smb = smem_u32(smg);
    const int tid = threadIdx.x;
    const int wid = tid >> 5;
    const int lane = tid & 31;
    const int g = lane >> 2;
    const int tig = lane & 3;
    const int m0 = blockIdx.x * 128;
    const int n0 = blockIdx.y * 128;
    const int wm = wid & 3;          // 4 m-warps (32 rows each)
    const int wn = wid >> 2;         // 2 n-warps (64 cols each)

    const __nv_bfloat16* Ah = (MODE == 0) ? g_xhi : g_hshi;
    const __nv_bfloat16* Al = (MODE == 0) ? g_xlo : g_hslo;
    const __nv_bfloat16* Bh = (MODE == 0) ? g_Wihi : g_Wohi;
    const __nv_bfloat16* Bl = (MODE == 0) ? g_Wilo : g_Wolo;

    const int lr0 = tid >> 3;         // base load row
    const int kel = (tid & 7) * 8;    // element offset within 64-wide chunk

    float acc[2][8][4];
#pragma unroll
    for (int mt = 0; mt < 2; mt++)
#pragma unroll
        for (int nt = 0; nt < 8; nt++)
#pragma unroll
            for (int r = 0; r < 4; r++) acc[mt][nt][r] = 0.f;

    const int NC = K >> 6;

    // chunk loader
    auto load_chunk = [&](int st, int c) {
        const int kbase = c * 64 + kel;
#pragma unroll
        for (int i = 0; i < 4; i++) {
            const int row = lr0 + i * 32;
            const uint32_t sw = swzg(row, kel * 2);
            const void* sa_h = Ah + (size_t)(m0 + row) * K + kbase;
            const void* sa_l = Al + (size_t)(m0 + row) * K + kbase;
            const void* sb_h = Bh + (size_t)(n0 + row) * K + kbase;
            const void* sb_l = Bl + (size_t)(n0 + row) * K + kbase;
            asm volatile("cp.async.cg.shared.global [%0], [%1], 16;"
                         :: "r"(smb + GOFF_AH(st) + sw), "l"(sa_h));
            asm volatile("cp.async.cg.shared.global [%0], [%1], 16;"
                         :: "r"(smb + GOFF_AL(st) + sw), "l"(sa_l));
            asm volatile("cp.async.cg.shared.global [%0], [%1], 16;"
                         :: "r"(smb + GOFF_BH(st) + sw), "l"(sb_h));
            asm volatile("cp.async.cg.shared.global [%0], [%1], 16;"
                         :: "r"(smb + GOFF_BL(st) + sw), "l"(sb_l));
        }
    };

    load_chunk(0, 0);
    asm volatile("cp.async.commit_group;" ::: "memory");

    for (int c = 0; c < NC; c++) {
        asm volatile("cp.async.wait_group 0;" ::: "memory");
        __syncthreads();
        if (c + 1 < NC) {
            load_chunk((c + 1) & 1, c + 1);
            asm volatile("cp.async.commit_group;" ::: "memory");
        }
        const int st = c & 1;
        const char* As_h = smg + GOFF_AH(st);
        const char* As_l = smg + GOFF_AL(st);
        const char* Bs_h = smg + GOFF_BH(st);
        const char* Bs_l = smg + GOFF_BL(st);

#pragma unroll
        for (int ks = 0; ks < 4; ks++) {
            const int kc = ks * 16 + tig * 2;
            uint32_t bhf[8][2], blf[8][2];
#pragma unroll
            for (int nt = 0; nt < 8; nt++) {
                const int rb = wn * 64 + nt * 8 + g;
                bhf[nt][0] = *(const uint32_t*)(Bs_h + swzg(rb, kc * 2));
                bhf[nt][1] = *(const uint32_t*)(Bs_h + swzg(rb, (kc + 8) * 2));
                blf[nt][0] = *(const uint32_t*)(Bs_l + swzg(rb, kc * 2));
                blf[nt][1] = *(const uint32_t*)(Bs_l + swzg(rb, (kc + 8) * 2));
            }
#pragma unroll
            for (int mt = 0; mt < 2; mt++) {
                uint32_t ah[4], al[4];
#pragma unroll
                for (int r = 0; r < 4; r++) {
                    const int rm = wm * 32 + mt * 16 + g + ((r & 1) ? 8 : 0);
                    const int kk = kc + ((r & 2) ? 8 : 0);
                    ah[r] = *(const uint32_t*)(As_h + swzg(rm, kk * 2));
                    al[r] = *(const uint32_t*)(As_l + swzg(rm, kk * 2));
                }
#pragma unroll
                for (int nt = 0; nt < 8; nt++) {
                    mma16816(acc[mt][nt], ah, bhf[nt]);
                    mma16816(acc[mt][nt], ah, blf[nt]);
                    mma16816(acc[mt][nt], al, bhf[nt]);
                }
            }
        }
        __syncthreads();
    }

    // epilogue
#pragma unroll
    for (int mt = 0; mt < 2; mt++) {
#pragma unroll
        for (int r2 = 0; r2 < 2; r2++) {
            const int m = m0 + wm * 32 + mt * 16 + g + r2 * 8;
#pragma unroll
            for (int nt = 0; nt < 8; nt++) {
                const int n = n0 + wn * 64 + nt * 8 + tig * 2;
                float2 bias;
                bias.x = b1[n];
                bias.y = b1[n + 1];
                if (MODE == 0) { bias.x += b2[n]; bias.y += b2[n + 1]; }
                float2 v;
                v.x = acc[mt][nt][r2 * 2 + 0] + bias.x;
                v.y = acc[mt][nt][r2 * 2 + 1] + bias.y;
                if (MODE == 0) {
                    const int b = m >> 9, s = m & 511;
                    *(float2*)&g_xi[((size_t)s * 64 + b) * 1024 + n] = v;
                } else {
                    const int s = m >> 6, b = m & 63;
                    *(float2*)&C[((size_t)b * 512 + s) * 512 + n] = v;
                }
            }
        }
    }
}

// ---------------------------------------------------------------------------
// Persistent recurrence (unchanged from R4, plus bf16 hi/lo h outputs)
// ---------------------------------------------------------------------------
#define OFF_WHL 0
#define OFF_HHh  131072
#define OFF_HLl  147456
#define OFF_RED 163840
#define RNN_SMEM_BYTES 180224

__device__ __forceinline__ int swz(int row, int kbyte) {
    return row * 2048 + (kbyte ^ ((row & 7) << 4));
}

__global__ __launch_bounds__(256, 1)
void rnn_persistent_kernel(const float* __restrict__ Wh)
{
    extern __shared__ char sm[];
    float* red = (float*)(sm + OFF_RED);

    const int tid = threadIdx.x;
    const int wid = tid >> 5;
    const int lane = tid & 31;
    const int g = lane >> 2;
    const int tig = lane & 3;
    const int cta = blockIdx.x;
    const int jt = cta & 15;
    const int bt = cta >> 4;
    const int j0 = jt * 64;
    const int b0 = bt * 8;
    const int kw0 = wid * 128;

    uint32_t a_hi[4][8][4];
#pragma unroll
    for (int mt = 0; mt < 4; mt++) {
#pragma unroll
        for (int ks = 0; ks < 8; ks++) {
#pragma unroll
            for (int r = 0; r < 4; r++) {
                const int jl = mt * 16 + g + ((r & 1) ? 8 : 0);
                const int k  = kw0 + ks * 16 + tig * 2 + ((r & 2) ? 8 : 0);
                const float2 w = *(const float2*)&Wh[(size_t)(j0 + jl) * HH + k];
                const uint32_t hi = pack_bf16(w.x, w.y);
                a_hi[mt][ks][r] = hi;
                const __nv_bfloat162 h2 = *(const __nv_bfloat162*)&hi;
                const uint32_t lo = pack_bf16(w.x - __bfloat162float(h2.x),
                                              w.y - __bfloat162float(h2.y));
                *(uint32_t*)(sm + OFF_WHL + swz(jl, k * 2)) = lo;
            }
        }
    }
    __syncthreads();

    for (int t = 0; t < SS; t++) {
        const int eb = tid >> 5;
        const int ej = (tid & 31) * 2;
        const float2 xiv = *(const float2*)
            &g_xi[(size_t)t * BB * HH + (size_t)(b0 + eb) * HH + j0 + ej];

        float h0, h1;
        if (t > 0) {
            if (tid < NBLK) {
                while (*(volatile unsigned*)&g_flags[tid * 32] < (unsigned)t) {}
            }
            __syncthreads();
            __threadfence();

            const float* hsrc = g_hs + (size_t)(t - 1) * BB * HH + (size_t)b0 * HH;
#pragma unroll
            for (int it = 0; it < 8; it++) {
                const int u = it * 256 + tid;
                const int b = u >> 8;
                const int k = (u & 255) * 4;
                const float4 v = __ldcg((const float4*)(hsrc + b * HH + k));
                uint2 vh, vl;
                vh.x = pack_bf16(v.x, v.y);
                vh.y = pack_bf16(v.z, v.w);
                const __nv_bfloat162 p0 = *(const __nv_bfloat162*)&vh.x;
                const __nv_bfloat162 p1 = *(const __nv_bfloat162*)&vh.y;
                vl.x = pack_bf16(v.x - __bfloat162float(p0.x),
                                 v.y - __bfloat162float(p0.y));
                vl.y = pack_bf16(v.z - __bfloat162float(p1.x),
                                 v.w - __bfloat162float(p1.y));
                const int off = swz(b, k * 2);
                *(uint2*)(sm + OFF_HHh + off) = vh;
                *(uint2*)(sm + OFF_HLl + off) = vl;
            }
            __syncthreads();

            float acc[4][4];
#pragma unroll
            for (int mt = 0; mt < 4; mt++)
#pragma unroll
                for (int r = 0; r < 4; r++) acc[mt][r] = 0.f;

#pragma unroll
            for (int ks = 0; ks < 8; ks++) {
                const int kc = kw0 + ks * 16 + tig * 2;
                uint32_t bh[2], bl[2];
                bh[0] = *(const uint32_t*)(sm + OFF_HHh + swz(g, kc * 2));
                bh[1] = *(const uint32_t*)(sm + OFF_HHh + swz(g, (kc + 8) * 2));
                bl[0] = *(const uint32_t*)(sm + OFF_HLl + swz(g, kc * 2));
                bl[1] = *(const uint32_t*)(sm + OFF_HLl + swz(g, (kc + 8) * 2));
#pragma unroll
                for (int mt = 0; mt < 4; mt++)
                    mma16816(acc[mt], a_hi[mt][ks], bh);
#pragma unroll
                for (int mt = 0; mt < 4; mt++)
                    mma16816(acc[mt], a_hi[mt][ks], bl);
#pragma unroll
                for (int mt = 0; mt < 4; mt++) {
                    uint32_t al[4];
#pragma unroll
                    for (int r = 0; r < 4; r++) {
                        const int jl = mt * 16 + g + ((r & 1) ? 8 : 0);
                        const int k  = kc + ((r & 2) ? 8 : 0);
                        al[r] = *(const uint32_t*)(sm + OFF_WHL + swz(jl, k * 2));
                    }
                    mma16816(acc[mt], al, bh);
                }
            }

            float* rw = red + wid * 512;
#pragma unroll
            for (int mt = 0; mt < 4; mt++) {
                const int jl = mt * 16 + g;
                rw[(tig * 2) * 64 + jl]         = acc[mt][0];
                rw[(tig * 2 + 1) * 64 + jl]     = acc[mt][1];
                rw[(tig * 2) * 64 + jl + 8]     = acc[mt][2];
                rw[(tig * 2 + 1) * 64 + jl + 8] = acc[mt][3];
            }
            __syncthreads();

            const int e = tid * 2;
            float s0 = 0.f, s1 = 0.f;
#pragma unroll
            for (int w = 0; w < 8; w++) {
                s0 += red[w * 512 + e];
                s1 += red[w * 512 + e + 1];
            }
            h0 = tanhf(s0 + xiv.x);
            h1 = tanhf(s1 + xiv.y);
        } else {
            h0 = tanhf(xiv.x);
            h1 = tanhf(xiv.y);
        }

        const size_t hoff = (size_t)t * BB * HH + (size_t)(b0 + eb) * HH + j0 + ej;
        *(float2*)&g_hs[hoff] = make_float2(h0, h1);
        const uint32_t ph = pack_bf16(h0, h1);
        const __nv_bfloat162 hv = *(const __nv_bfloat162*)&ph;
        const uint32_t pl = pack_bf16(h0 - __bfloat162float(hv.x),
                                      h1 - __bfloat162float(hv.y));
        *(uint32_t*)&g_hshi[hoff] = ph;
        *(uint32_t*)&g_hslo[hoff] = pl;

        if (t < SS - 1) {
            __threadfence();
            __syncthreads();
            if (tid == 0) {
                atomicExch((unsigned*)&g_flags[cta * 32], (unsigned)(t + 1));
            }
        }
    }
}

__global__ void copy_hlast_kernel(float* __restrict__ dst)
{
    const int i = blockIdx.x * blockDim.x + threadIdx.x;
    dst[i] = g_hs[(size_t)(SS - 1) * BB * HH + i];
}

// ---------------------------------------------------------------------------
extern "C" void kernel_launch(void* const* d_in, const int* in_sizes, int n_in,
                              void* d_out, int out_size)
{
    const float* x  = (const float*)d_in[0];
    const float* Wi = (const float*)d_in[1];
    const float* bi = (const float*)d_in[2];
    const float* Wh = (const float*)d_in[3];
    const float* bh = (const float*)d_in[4];
    const float* Wo = (const float*)d_in[5];
    const float* bo = (const float*)d_in[6];
    float* out = (float*)d_out;

    cudaFuncSetAttribute(rnn_persistent_kernel,
                         cudaFuncAttributeMaxDynamicSharedMemorySize, RNN_SMEM_BYTES);
    cudaFuncSetAttribute(gemm_tc_kernel<0>,
                         cudaFuncAttributeMaxDynamicSharedMemorySize, GEMM_SMEM);
    cudaFuncSetAttribute(gemm_tc_kernel<1>,
                         cudaFuncAttributeMaxDynamicSharedMemorySize, GEMM_SMEM);

    // 0) fp32 -> bf16 hi/lo splits
    split_kernel<0><<<(BB * SS * II) / 1024, 256>>>(x);
    split_kernel<1><<<(HH * II) / 1024, 256>>>(Wi);
    split_kernel<2><<<(OO * HH) / 1024, 256>>>(Wo);

    // 1) xi = x @ Wi^T + bi + bh  (tensor core)
    dim3 g1((BB * SS) / 128, HH / 128);
    gemm_tc_kernel<0><<<g1, 256, GEMM_SMEM>>>(bi, bh, nullptr, II);

    // 2) recurrence
    reset_flags_kernel<<<1, NBLK>>>();
    rnn_persistent_kernel<<<NBLK, 256, RNN_SMEM_BYTES>>>(Wh);

    // 3) out = hs @ Wo^T + bo  (tensor core)
    dim3 g2((BB * SS) / 128, OO / 128);
    gemm_tc_kernel<1><<<g2, 256, GEMM_SMEM>>>(bo, nullptr, out, HH);

    // 4) h_last appended if expected
    if (out_size >= BB * SS * OO + BB * HH) {
        copy_hlast_kernel<<<(BB * HH) / 256, 256>>>(out + (size_t)BB * SS * OO);
    }
}

// round 6
// speedup vs baseline: 4.2974x; 1.1653x over previous
#include <cuda_runtime.h>
#include <cuda_bf16.h>
#include <math.h>
#include <stdint.h>

// Problem dims
#define BB 64
#define SS 512
#define II 512
#define HH 1024
#define OO 512
#define NBLK 128

// Scratch (device globals; no allocations)
__device__ float g_xi[SS * BB * HH];               // [s][b][h]
__device__ float g_hs[SS * BB * HH];               // fp32 (only t=SS-1 written)
__device__ __nv_bfloat16 g_hshi[SS * BB * HH];     // hs split hi
__device__ __nv_bfloat16 g_hslo[SS * BB * HH];     // hs split lo
__device__ __nv_bfloat16 g_xhi[BB * SS * II];
__device__ __nv_bfloat16 g_xlo[BB * SS * II];
__device__ __nv_bfloat16 g_Wihi[HH * II];
__device__ __nv_bfloat16 g_Wilo[HH * II];
__device__ __nv_bfloat16 g_Wohi[OO * HH];
__device__ __nv_bfloat16 g_Wolo[OO * HH];
__device__ unsigned g_flags[NBLK * 32];

__global__ void reset_flags_kernel() { g_flags[threadIdx.x * 32] = 0u; }

// ---------------------------------------------------------------------------
// helpers
// ---------------------------------------------------------------------------
__device__ __forceinline__ uint32_t smem_u32(const void* p) {
    return (uint32_t)__cvta_generic_to_shared(p);
}
__device__ __forceinline__ void mma16816(float d[4], const uint32_t a[4],
                                         const uint32_t b[2])
{
    asm volatile(
        "mma.sync.aligned.m16n8k16.row.col.f32.bf16.bf16.f32 "
        "{%0,%1,%2,%3}, {%4,%5,%6,%7}, {%8,%9}, {%0,%1,%2,%3};"
        : "+f"(d[0]), "+f"(d[1]), "+f"(d[2]), "+f"(d[3])
        : "r"(a[0]), "r"(a[1]), "r"(a[2]), "r"(a[3]), "r"(b[0]), "r"(b[1]));
}
__device__ __forceinline__ uint32_t pack_bf16(float f0, float f1)
{
    __nv_bfloat162 v;
    v.x = __float2bfloat16(f0);
    v.y = __float2bfloat16(f1);
    return *(uint32_t*)&v;
}

// ---------------------------------------------------------------------------
// fp32 -> (hi,lo) bf16 split kernels. WHICH: 0=x, 1=Wi, 2=Wo
// ---------------------------------------------------------------------------
template <int WHICH>
__global__ void split_kernel(const float* __restrict__ src)
{
    __nv_bfloat16* hi = (WHICH == 0) ? g_xhi : (WHICH == 1) ? g_Wihi : g_Wohi;
    __nv_bfloat16* lo = (WHICH == 0) ? g_xlo : (WHICH == 1) ? g_Wilo : g_Wolo;
    const int i = (blockIdx.x * blockDim.x + threadIdx.x) * 4;
    const float4 v = *(const float4*)(src + i);
    uint2 h, l;
    h.x = pack_bf16(v.x, v.y);
    h.y = pack_bf16(v.z, v.w);
    const __nv_bfloat162 p0 = *(const __nv_bfloat162*)&h.x;
    const __nv_bfloat162 p1 = *(const __nv_bfloat162*)&h.y;
    l.x = pack_bf16(v.x - __bfloat162float(p0.x), v.y - __bfloat162float(p0.y));
    l.y = pack_bf16(v.z - __bfloat162float(p1.x), v.w - __bfloat162float(p1.y));
    *(uint2*)(hi + i) = h;
    *(uint2*)(lo + i) = l;
}

// ---------------------------------------------------------------------------
// Tensor-core bf16x3 GEMM (unchanged from R5)
// ---------------------------------------------------------------------------
#define GOFF_AH(st) ((st) * 65536 + 0)
#define GOFF_AL(st) ((st) * 65536 + 16384)
#define GOFF_BH(st) ((st) * 65536 + 32768)
#define GOFF_BL(st) ((st) * 65536 + 49152)
#define GEMM_SMEM 131072

__device__ __forceinline__ int swzg(int row, int kb) {
    return row * 128 + (kb ^ ((row & 7) << 4));
}

template <int MODE>
__global__ __launch_bounds__(256, 1)
void gemm_tc_kernel(const float* __restrict__ b1, const float* __restrict__ b2,
                    float* __restrict__ C, int K)
{
    extern __shared__ char smg[];
    const uint32_t smb = smem_u32(smg);
    const int tid = threadIdx.x;
    const int wid = tid >> 5;
    const int lane = tid & 31;
    const int g = lane >> 2;
    const int tig = lane & 3;
    const int m0 = blockIdx.x * 128;
    const int n0 = blockIdx.y * 128;
    const int wm = wid & 3;
    const int wn = wid >> 2;

    const __nv_bfloat16* Ah = (MODE == 0) ? g_xhi : g_hshi;
    const __nv_bfloat16* Al = (MODE == 0) ? g_xlo : g_hslo;
    const __nv_bfloat16* Bh = (MODE == 0) ? g_Wihi : g_Wohi;
    const __nv_bfloat16* Bl = (MODE == 0) ? g_Wilo : g_Wolo;

    const int lr0 = tid >> 3;
    const int kel = (tid & 7) * 8;

    float acc[2][8][4];
#pragma unroll
    for (int mt = 0; mt < 2; mt++)
#pragma unroll
        for (int nt = 0; nt < 8; nt++)
#pragma unroll
            for (int r = 0; r < 4; r++) acc[mt][nt][r] = 0.f;

    const int NC = K >> 6;

    auto load_chunk = [&](int st, int c) {
        const int kbase = c * 64 + kel;
#pragma unroll
        for (int i = 0; i < 4; i++) {
            const int row = lr0 + i * 32;
            const uint32_t sw = swzg(row, kel * 2);
            const void* sa_h = Ah + (size_t)(m0 + row) * K + kbase;
            const void* sa_l = Al + (size_t)(m0 + row) * K + kbase;
            const void* sb_h = Bh + (size_t)(n0 + row) * K + kbase;
            const void* sb_l = Bl + (size_t)(n0 + row) * K + kbase;
            asm volatile("cp.async.cg.shared.global [%0], [%1], 16;"
                         :: "r"(smb + GOFF_AH(st) + sw), "l"(sa_h));
            asm volatile("cp.async.cg.shared.global [%0], [%1], 16;"
                         :: "r"(smb + GOFF_AL(st) + sw), "l"(sa_l));
            asm volatile("cp.async.cg.shared.global [%0], [%1], 16;"
                         :: "r"(smb + GOFF_BH(st) + sw), "l"(sb_h));
            asm volatile("cp.async.cg.shared.global [%0], [%1], 16;"
                         :: "r"(smb + GOFF_BL(st) + sw), "l"(sb_l));
        }
    };

    load_chunk(0, 0);
    asm volatile("cp.async.commit_group;" ::: "memory");

    for (int c = 0; c < NC; c++) {
        asm volatile("cp.async.wait_group 0;" ::: "memory");
        __syncthreads();
        if (c + 1 < NC) {
            load_chunk((c + 1) & 1, c + 1);
            asm volatile("cp.async.commit_group;" ::: "memory");
        }
        const int st = c & 1;
        const char* As_h = smg + GOFF_AH(st);
        const char* As_l = smg + GOFF_AL(st);
        const char* Bs_h = smg + GOFF_BH(st);
        const char* Bs_l = smg + GOFF_BL(st);

#pragma unroll
        for (int ks = 0; ks < 4; ks++) {
            const int kc = ks * 16 + tig * 2;
            uint32_t bhf[8][2], blf[8][2];
#pragma unroll
            for (int nt = 0; nt < 8; nt++) {
                const int rb = wn * 64 + nt * 8 + g;
                bhf[nt][0] = *(const uint32_t*)(Bs_h + swzg(rb, kc * 2));
                bhf[nt][1] = *(const uint32_t*)(Bs_h + swzg(rb, (kc + 8) * 2));
                blf[nt][0] = *(const uint32_t*)(Bs_l + swzg(rb, kc * 2));
                blf[nt][1] = *(const uint32_t*)(Bs_l + swzg(rb, (kc + 8) * 2));
            }
#pragma unroll
            for (int mt = 0; mt < 2; mt++) {
                uint32_t ah[4], al[4];
#pragma unroll
                for (int r = 0; r < 4; r++) {
                    const int rm = wm * 32 + mt * 16 + g + ((r & 1) ? 8 : 0);
                    const int kk = kc + ((r & 2) ? 8 : 0);
                    ah[r] = *(const uint32_t*)(As_h + swzg(rm, kk * 2));
                    al[r] = *(const uint32_t*)(As_l + swzg(rm, kk * 2));
                }
#pragma unroll
                for (int nt = 0; nt < 8; nt++) {
                    mma16816(acc[mt][nt], ah, bhf[nt]);
                    mma16816(acc[mt][nt], ah, blf[nt]);
                    mma16816(acc[mt][nt], al, bhf[nt]);
                }
            }
        }
        __syncthreads();
    }

#pragma unroll
    for (int mt = 0; mt < 2; mt++) {
#pragma unroll
        for (int r2 = 0; r2 < 2; r2++) {
            const int m = m0 + wm * 32 + mt * 16 + g + r2 * 8;
#pragma unroll
            for (int nt = 0; nt < 8; nt++) {
                const int n = n0 + wn * 64 + nt * 8 + tig * 2;
                float2 bias;
                bias.x = b1[n];
                bias.y = b1[n + 1];
                if (MODE == 0) { bias.x += b2[n]; bias.y += b2[n + 1]; }
                float2 v;
                v.x = acc[mt][nt][r2 * 2 + 0] + bias.x;
                v.y = acc[mt][nt][r2 * 2 + 1] + bias.y;
                if (MODE == 0) {
                    const int b = m >> 9, s = m & 511;
                    *(float2*)&g_xi[((size_t)s * 64 + b) * 1024 + n] = v;
                } else {
                    const int s = m >> 6, b = m & 63;
                    *(float2*)&C[((size_t)b * 512 + s) * 512 + n] = v;
                }
            }
        }
    }
}

// ---------------------------------------------------------------------------
// Persistent recurrence: 8 independent groups of 16 CTAs (one per b-slice).
// Group barrier (16 flags, acquire/release), bf16 staging, fp32 h only at end.
// ---------------------------------------------------------------------------
#define OFF_WHL 0
#define OFF_HHh  131072
#define OFF_HLl  147456
#define OFF_RED 163840
#define RNN_SMEM_BYTES 180224

__device__ __forceinline__ int swz(int row, int kbyte) {
    return row * 2048 + (kbyte ^ ((row & 7) << 4));
}

__global__ __launch_bounds__(256, 1)
void rnn_persistent_kernel(const float* __restrict__ Wh)
{
    extern __shared__ char sm[];
    float* red = (float*)(sm + OFF_RED);

    const int tid = threadIdx.x;
    const int wid = tid >> 5;
    const int lane = tid & 31;
    const int g = lane >> 2;
    const int tig = lane & 3;
    const int cta = blockIdx.x;
    const int jt = cta & 15;
    const int bt = cta >> 4;
    const int j0 = jt * 64;
    const int b0 = bt * 8;
    const int kw0 = wid * 128;
    const int grp0 = bt * 16;       // first CTA of my 16-CTA group

    // one-time: Wh_hi -> regs, Wh_lo -> smem
    uint32_t a_hi[4][8][4];
#pragma unroll
    for (int mt = 0; mt < 4; mt++) {
#pragma unroll
        for (int ks = 0; ks < 8; ks++) {
#pragma unroll
            for (int r = 0; r < 4; r++) {
                const int jl = mt * 16 + g + ((r & 1) ? 8 : 0);
                const int k  = kw0 + ks * 16 + tig * 2 + ((r & 2) ? 8 : 0);
                const float2 w = *(const float2*)&Wh[(size_t)(j0 + jl) * HH + k];
                const uint32_t hi = pack_bf16(w.x, w.y);
                a_hi[mt][ks][r] = hi;
                const __nv_bfloat162 h2 = *(const __nv_bfloat162*)&hi;
                const uint32_t lo = pack_bf16(w.x - __bfloat162float(h2.x),
                                              w.y - __bfloat162float(h2.y));
                *(uint32_t*)(sm + OFF_WHL + swz(jl, k * 2)) = lo;
            }
        }
    }
    __syncthreads();

    for (int t = 0; t < SS; t++) {
        const int eb = tid >> 5;
        const int ej = (tid & 31) * 2;
        const float2 xiv = *(const float2*)
            &g_xi[(size_t)t * BB * HH + (size_t)(b0 + eb) * HH + j0 + ej];

        float h0, h1;
        if (t > 0) {
            // group barrier: threads 0..15 poll the 16 group flags (acquire)
            if (tid < 16) {
                const unsigned* fp = &g_flags[(grp0 + tid) * 32];
                unsigned v;
                do {
                    asm volatile("ld.acquire.gpu.global.u32 %0, [%1];"
                                 : "=r"(v) : "l"(fp));
                } while (v < (unsigned)t);
            }
            __syncthreads();

            // stage h(t-1) hi/lo bf16 directly into swizzled SMEM
            const __nv_bfloat16* srcH =
                g_hshi + (size_t)(t - 1) * BB * HH + (size_t)b0 * HH;
            const __nv_bfloat16* srcL =
                g_hslo + (size_t)(t - 1) * BB * HH + (size_t)b0 * HH;
#pragma unroll
            for (int it = 0; it < 4; it++) {
                const int u = it * 256 + tid;       // [0,1024), 8 bf16 each
                const int b = u >> 7;
                const int k = (u & 127) * 8;
                const uint4 vh = __ldcg((const uint4*)(srcH + b * HH + k));
                const uint4 vl = __ldcg((const uint4*)(srcL + b * HH + k));
                const int off = swz(b, k * 2);
                *(uint4*)(sm + OFF_HHh + off) = vh;
                *(uint4*)(sm + OFF_HLl + off) = vl;
            }
            __syncthreads();

            // tensor-core mainloop (k-split over 8 warps)
            float acc[4][4];
#pragma unroll
            for (int mt = 0; mt < 4; mt++)
#pragma unroll
                for (int r = 0; r < 4; r++) acc[mt][r] = 0.f;

#pragma unroll
            for (int ks = 0; ks < 8; ks++) {
                const int kc = kw0 + ks * 16 + tig * 2;
                uint32_t bh[2], bl[2];
                bh[0] = *(const uint32_t*)(sm + OFF_HHh + swz(g, kc * 2));
                bh[1] = *(const uint32_t*)(sm + OFF_HHh + swz(g, (kc + 8) * 2));
                bl[0] = *(const uint32_t*)(sm + OFF_HLl + swz(g, kc * 2));
                bl[1] = *(const uint32_t*)(sm + OFF_HLl + swz(g, (kc + 8) * 2));
#pragma unroll
                for (int mt = 0; mt < 4; mt++)
                    mma16816(acc[mt], a_hi[mt][ks], bh);
#pragma unroll
                for (int mt = 0; mt < 4; mt++)
                    mma16816(acc[mt], a_hi[mt][ks], bl);
#pragma unroll
                for (int mt = 0; mt < 4; mt++) {
                    uint32_t al[4];
#pragma unroll
                    for (int r = 0; r < 4; r++) {
                        const int jl = mt * 16 + g + ((r & 1) ? 8 : 0);
                        const int k  = kc + ((r & 2) ? 8 : 0);
                        al[r] = *(const uint32_t*)(sm + OFF_WHL + swz(jl, k * 2));
                    }
                    mma16816(acc[mt], al, bh);
                }
            }

            // cross-warp k-reduction
            float* rw = red + wid * 512;
#pragma unroll
            for (int mt = 0; mt < 4; mt++) {
                const int jl = mt * 16 + g;
                rw[(tig * 2) * 64 + jl]         = acc[mt][0];
                rw[(tig * 2 + 1) * 64 + jl]     = acc[mt][1];
                rw[(tig * 2) * 64 + jl + 8]     = acc[mt][2];
                rw[(tig * 2 + 1) * 64 + jl + 8] = acc[mt][3];
            }
            __syncthreads();

            const int e = tid * 2;
            float s0 = 0.f, s1 = 0.f;
#pragma unroll
            for (int w = 0; w < 8; w++) {
                const float2 v = *(const float2*)&red[w * 512 + e];
                s0 += v.x;
                s1 += v.y;
            }
            h0 = tanhf(s0 + xiv.x);
            h1 = tanhf(s1 + xiv.y);
        } else {
            h0 = tanhf(xiv.x);
            h1 = tanhf(xiv.y);
        }

        const size_t hoff = (size_t)t * BB * HH + (size_t)(b0 + eb) * HH + j0 + ej;
        const uint32_t ph = pack_bf16(h0, h1);
        const __nv_bfloat162 hv = *(const __nv_bfloat162*)&ph;
        const uint32_t pl = pack_bf16(h0 - __bfloat162float(hv.x),
                                      h1 - __bfloat162float(hv.y));
        *(uint32_t*)&g_hshi[hoff] = ph;
        *(uint32_t*)&g_hslo[hoff] = pl;
        if (t == SS - 1) {
            *(float2*)&g_hs[hoff] = make_float2(h0, h1);
        }

        if (t < SS - 1) {
            __syncthreads();        // all h(t) stores of this CTA issued
            if (tid == 0) {
                asm volatile("st.release.gpu.global.u32 [%0], %1;"
                             :: "l"(&g_flags[cta * 32]), "r"((unsigned)(t + 1))
                             : "memory");
            }
        }
    }
}

__global__ void copy_hlast_kernel(float* __restrict__ dst)
{
    const int i = blockIdx.x * blockDim.x + threadIdx.x;
    dst[i] = g_hs[(size_t)(SS - 1) * BB * HH + i];
}

// ---------------------------------------------------------------------------
extern "C" void kernel_launch(void* const* d_in, const int* in_sizes, int n_in,
                              void* d_out, int out_size)
{
    const float* x  = (const float*)d_in[0];
    const float* Wi = (const float*)d_in[1];
    const float* bi = (const float*)d_in[2];
    const float* Wh = (const float*)d_in[3];
    const float* bh = (const float*)d_in[4];
    const float* Wo = (const float*)d_in[5];
    const float* bo = (const float*)d_in[6];
    float* out = (float*)d_out;

    cudaFuncSetAttribute(rnn_persistent_kernel,
                         cudaFuncAttributeMaxDynamicSharedMemorySize, RNN_SMEM_BYTES);
    cudaFuncSetAttribute(gemm_tc_kernel<0>,
                         cudaFuncAttributeMaxDynamicSharedMemorySize, GEMM_SMEM);
    cudaFuncSetAttribute(gemm_tc_kernel<1>,
                         cudaFuncAttributeMaxDynamicSharedMemorySize, GEMM_SMEM);

    // 0) fp32 -> bf16 hi/lo splits
    split_kernel<0><<<(BB * SS * II) / 1024, 256>>>(x);
    split_kernel<1><<<(HH * II) / 1024, 256>>>(Wi);
    split_kernel<2><<<(OO * HH) / 1024, 256>>>(Wo);

    // 1) xi = x @ Wi^T + bi + bh  (tensor core)
    dim3 g1((BB * SS) / 128, HH / 128);
    gemm_tc_kernel<0><<<g1, 256, GEMM_SMEM>>>(bi, bh, nullptr, II);

    // 2) recurrence
    reset_flags_kernel<<<1, NBLK>>>();
    rnn_persistent_kernel<<<NBLK, 256, RNN_SMEM_BYTES>>>(Wh);

    // 3) out = hs @ Wo^T + bo  (tensor core)
    dim3 g2((BB * SS) / 128, OO / 128);
    gemm_tc_kernel<1><<<g2, 256, GEMM_SMEM>>>(bo, nullptr, out, HH);

    // 4) h_last appended if expected
    if (out_size >= BB * SS * OO + BB * HH) {
        copy_hlast_kernel<<<(BB * HH) / 256, 256>>>(out + (size_t)BB * SS * OO);
    }
}